// round 9
// baseline (speedup 1.0000x reference)
#include <cuda_runtime.h>
#include <math.h>

// ---------------------------------------------------------------------------
// Problem constants
// ---------------------------------------------------------------------------
constexpr int B_ = 32, T_ = 60, I_ = 577, H_ = 768, P_ = 384, G_ = 256, C_ = 128;
constexpr int NN  = I_ + T_;              // 637
constexpr int BT  = B_ * T_;              // 1920
constexpr int BI  = B_ * I_;              // 18464
constexpr int BNN = B_ * NN;              // 20384
constexpr size_t BNC = (size_t)BNN * C_;  // 2609152

// ---------------------------------------------------------------------------
// Packed fp32x2 helpers (sm_103a: fma.rn.f32x2 — 2 IEEE fp32 FMAs per issue)
// ---------------------------------------------------------------------------
__device__ __forceinline__ unsigned long long pack2(float v) {
    unsigned long long r;
    asm("mov.b64 %0, {%1, %1};" : "=l"(r) : "f"(v));
    return r;
}
__device__ __forceinline__ void fma2(unsigned long long& d,
                                     unsigned long long a, unsigned long long b) {
    asm("fma.rn.f32x2 %0, %1, %2, %0;" : "+l"(d) : "l"(a), "l"(b));
}
__device__ __forceinline__ float2 unpack2(unsigned long long v) {
    float2 f;
    asm("mov.b64 {%0, %1}, %2;" : "=f"(f.x), "=f"(f.y) : "l"(v));
    return f;
}

// ---------------------------------------------------------------------------
// Scratch layout (single static __device__ array; no allocations anywhere)
// ---------------------------------------------------------------------------
constexpr size_t SZ_PT = (size_t)BT * H_;
constexpr size_t SZ_PV = (size_t)BI * H_;
constexpr size_t SZ_X  = (size_t)BNN * P_;
constexpr size_t SZ_H  = (size_t)BNN * G_;

constexpr size_t OFF_PRIV_T = 0;
constexpr size_t OFF_PRIV_V = OFF_PRIV_T + SZ_PT;
constexpr size_t OFF_SHAR_T = OFF_PRIV_V + SZ_PV;
constexpr size_t OFF_SHAR_V = OFF_SHAR_T + SZ_PT;
constexpr size_t OFF_X      = OFF_SHAR_V + SZ_PV;
constexpr size_t OFF_H      = OFF_X + SZ_X;
constexpr size_t OFF_GOUT   = OFF_H + SZ_H;
constexpr size_t OFF_EL     = OFF_GOUT + SZ_H;
constexpr size_t OFF_ER     = OFF_EL + BNN;
constexpr size_t OFF_HGI    = OFF_ER + BNN;
constexpr size_t OFF_HGT    = OFF_HGI + (size_t)B_ * P_;
constexpr size_t OFF_KL     = OFF_HGT + (size_t)B_ * P_;
constexpr size_t SCRATCH_TOTAL = OFF_KL + 64;

__device__ float g_scratch[SCRATCH_TOTAL];

// ---------------------------------------------------------------------------
// GEMM: C = act(A[M,K] @ W[K,N] + bias), 128x128x8 tiling, 8x8 per thread,
// 256 threads, register-prefetch double buffering, packed f32x2 inner loop
// (32 FFMA2 + 8 packs per kk instead of 64 scalar FFMA).
// Optional output row remap for the concat([proj_v, proj_t]) layout:
//   orow = (row / rpb) * nper + off + row % rpb   (when rpb > 0)
// Requires: K % 8 == 0, N % 128 == 0 (true for all shapes here). M guarded.
// ---------------------------------------------------------------------------
constexpr int BM = 128, BN = 128, BKK = 8;

template<int ACT>  // 0 = none, 1 = sigmoid, 2 = relu
__global__ __launch_bounds__(256)
void gemm_kernel(const float* __restrict__ A, const float* __restrict__ W,
                 const float* __restrict__ bias, float* __restrict__ C,
                 int M, int K, int Nn, int rpb, int off, int nper)
{
    __shared__ __align__(16) float As[BKK][BM];   // transposed A tile: As[k][m]
    __shared__ __align__(16) float Bs[BKK][BN];   // Bs[k][n]

    const int tid = threadIdx.x;
    const int ty = tid >> 4, tx = tid & 15;        // 16x16 thread grid
    const int m0 = blockIdx.y * BM;
    const int n0 = blockIdx.x * BN;

    // A loader: 128 rows x 8 k -> 1 float4 per thread (along K)
    const int a_row = tid >> 1;            // 0..127
    const int a_kc  = (tid & 1) << 2;      // 0 or 4
    // B loader: 8 k-rows x 128 cols -> 1 float4 per thread (along N)
    const int b_kr  = tid >> 5;            // 0..7
    const int b_c   = (tid & 31) << 2;     // 0..124

    const bool a_ok = (m0 + a_row < M);
    const float* a_src = A + (size_t)(m0 + a_row) * K + a_kc;
    const float* b_src = W + (size_t)b_kr * Nn + n0 + b_c;

    // acc2[i][jp]: packed pair (col 2*jp, 2*jp+1) of output row i
    unsigned long long acc2[8][4];
    #pragma unroll
    for (int i = 0; i < 8; i++)
        #pragma unroll
        for (int j = 0; j < 4; j++) acc2[i][j] = 0ULL;

    // Prologue: fetch tile 0 into registers
    float4 a_pref = a_ok ? *(const float4*)(a_src)
                         : make_float4(0.f, 0.f, 0.f, 0.f);
    float4 b_pref = *(const float4*)(b_src);

    for (int k0 = 0; k0 < K; k0 += BKK) {
        // Deposit prefetched tile into smem
        As[a_kc + 0][a_row] = a_pref.x;
        As[a_kc + 1][a_row] = a_pref.y;
        As[a_kc + 2][a_row] = a_pref.z;
        As[a_kc + 3][a_row] = a_pref.w;
        *(float4*)&Bs[b_kr][b_c] = b_pref;
        __syncthreads();

        // Issue next tile's global loads before the compute loop
        const int kn = k0 + BKK;
        if (kn < K) {
            a_pref = a_ok ? *(const float4*)(a_src + kn)
                          : make_float4(0.f, 0.f, 0.f, 0.f);
            b_pref = *(const float4*)(b_src + (size_t)BKK * Nn);
            b_src += (size_t)BKK * Nn;
        }

        #pragma unroll
        for (int kk = 0; kk < BKK; kk++) {
            float4 a0 = *(const float4*)&As[kk][ty << 3];
            float4 a1 = *(const float4*)&As[kk][(ty << 3) + 4];
            // B as two 16B loads, each yielding 2 packed f32x2 operands
            ulonglong2 b01 = *(const ulonglong2*)&Bs[kk][tx << 3];
            ulonglong2 b23 = *(const ulonglong2*)&Bs[kk][(tx << 3) + 4];
            unsigned long long ap[8] = {
                pack2(a0.x), pack2(a0.y), pack2(a0.z), pack2(a0.w),
                pack2(a1.x), pack2(a1.y), pack2(a1.z), pack2(a1.w)
            };
            #pragma unroll
            for (int i = 0; i < 8; i++) {
                fma2(acc2[i][0], ap[i], b01.x);
                fma2(acc2[i][1], ap[i], b01.y);
                fma2(acc2[i][2], ap[i], b23.x);
                fma2(acc2[i][3], ap[i], b23.y);
            }
        }
        __syncthreads();
    }

    #pragma unroll
    for (int i = 0; i < 8; i++) {
        int row = m0 + (ty << 3) + i;
        if (row >= M) continue;
        int orow = (rpb > 0) ? ((row / rpb) * nper + off + (row % rpb)) : row;
        float* crow = C + (size_t)orow * Nn + n0 + (tx << 3);
        #pragma unroll
        for (int half = 0; half < 2; half++) {
            float2 p0 = unpack2(acc2[i][half * 2 + 0]);
            float2 p1 = unpack2(acc2[i][half * 2 + 1]);
            float cc[4] = {p0.x, p0.y, p1.x, p1.y};
            float4 v;
            float* vp = &v.x;
            #pragma unroll
            for (int j = 0; j < 4; j++) {
                float c = cc[j];
                if (bias) c += bias[n0 + (tx << 3) + half * 4 + j];
                if (ACT == 1) c = 1.f / (1.f + __expf(-c));
                if (ACT == 2) c = fmaxf(c, 0.f);
                vp[j] = c;
            }
            *(float4*)(crow + half * 4) = v;
        }
    }
}

// ---------------------------------------------------------------------------
// el/er: per-row dot of h[row, :G] with al / ar. One warp per row.
// ---------------------------------------------------------------------------
__global__ void eler_kernel(const float* __restrict__ h,
                            const float* __restrict__ al,
                            const float* __restrict__ ar,
                            float* __restrict__ el, float* __restrict__ er)
{
    int row  = blockIdx.x * 8 + (threadIdx.x >> 5);
    int lane = threadIdx.x & 31;
    if (row >= BNN) return;
    const float* hr = h + (size_t)row * G_;
    float se = 0.f, sr = 0.f;
    #pragma unroll
    for (int j = 0; j < G_ / 32; j++) {
        float hv = hr[lane + 32 * j];
        se += hv * al[lane + 32 * j];
        sr += hv * ar[lane + 32 * j];
    }
    #pragma unroll
    for (int o = 16; o; o >>= 1) {
        se += __shfl_xor_sync(0xffffffffu, se, o);
        sr += __shfl_xor_sync(0xffffffffu, sr, o);
    }
    if (lane == 0) { el[row] = se; er[row] = sr; }
}

// ---------------------------------------------------------------------------
// Fused GAT: for each (b, dst): softmax over src != dst of
// leaky_relu(el[src] + er[dst]), then out[g] = elu(sum_src a * h[src,g]).
// One block handles DT=16 dst rows (each warp runs 2 softmaxes), then all
// 256 threads (g = tid) do the weighted sum with 16-way h reuse.
// s_w stored [src][16]; hot loop: 1 LDG + 4 LDS.128 + 1 pack + 8 FFMA2 / src.
// Softmax uses __expf: weights are normalized, so 2-ulp exp error is
// invisible at the 1e-3 gate.
// ---------------------------------------------------------------------------
constexpr int DT = 16;

__global__ __launch_bounds__(256)
void gat_kernel(const float* __restrict__ h, const float* __restrict__ el,
                const float* __restrict__ er, float* __restrict__ gout)
{
    __shared__ float s_el[NN];
    __shared__ __align__(16) float s_w[NN][DT];
    __shared__ float s_den[DT];

    const int b   = blockIdx.y;
    const int d0  = blockIdx.x * DT;
    const int tid = threadIdx.x;

    for (int i = tid; i < NN; i += 256) s_el[i] = el[(size_t)b * NN + i];
    __syncthreads();

    const int w = tid >> 5, lane = tid & 31;
    #pragma unroll
    for (int sub = 0; sub < 2; sub++) {
        const int dl  = w + sub * 8;     // 0..15
        const int dst = d0 + dl;
        if (dst < NN) {
            float erd = er[(size_t)b * NN + dst];
            float m = -1e30f;
            for (int src = lane; src < NN; src += 32) {
                if (src == dst) continue;
                float s  = s_el[src] + erd;
                float lr = s > 0.f ? s : 0.2f * s;
                m = fmaxf(m, lr);
            }
            #pragma unroll
            for (int o = 16; o; o >>= 1)
                m = fmaxf(m, __shfl_xor_sync(0xffffffffu, m, o));
            float den = 0.f;
            for (int src = lane; src < NN; src += 32) {
                float s  = s_el[src] + erd;
                float lr = s > 0.f ? s : 0.2f * s;
                float wv = (src == dst) ? 0.f : __expf(lr - m);
                s_w[src][dl] = wv;
                den += wv;
            }
            #pragma unroll
            for (int o = 16; o; o >>= 1)
                den += __shfl_xor_sync(0xffffffffu, den, o);
            if (lane == 0) s_den[dl] = den;
        } else {
            for (int src = lane; src < NN; src += 32) s_w[src][dl] = 0.f;
            if (lane == 0) s_den[dl] = 1.f;
        }
    }
    __syncthreads();

    // weighted sum: g = tid (G == 256 == blockDim); acc pairs over dst
    unsigned long long acc2[8];
    #pragma unroll
    for (int d = 0; d < 8; d++) acc2[d] = 0ULL;

    const float* hb = h + (size_t)b * NN * G_ + tid;
    for (int src = 0; src < NN; src++) {
        float hv = hb[(size_t)src * G_];
        unsigned long long hp = pack2(hv);
        ulonglong2 w01 = *(const ulonglong2*)&s_w[src][0];
        ulonglong2 w23 = *(const ulonglong2*)&s_w[src][4];
        ulonglong2 w45 = *(const ulonglong2*)&s_w[src][8];
        ulonglong2 w67 = *(const ulonglong2*)&s_w[src][12];
        fma2(acc2[0], hp, w01.x); fma2(acc2[1], hp, w01.y);
        fma2(acc2[2], hp, w23.x); fma2(acc2[3], hp, w23.y);
        fma2(acc2[4], hp, w45.x); fma2(acc2[5], hp, w45.y);
        fma2(acc2[6], hp, w67.x); fma2(acc2[7], hp, w67.y);
    }
    #pragma unroll
    for (int dp = 0; dp < 8; dp++) {
        float2 pr = unpack2(acc2[dp]);
        float av[2] = {pr.x, pr.y};
        #pragma unroll
        for (int half = 0; half < 2; half++) {
            int d = dp * 2 + half;
            int dst2 = d0 + d;
            if (dst2 < NN) {
                float o = av[half] / s_den[d];
                gout[((size_t)b * NN + dst2) * G_ + tid] = o > 0.f ? o : expm1f(o);
            }
        }
    }
}

// ---------------------------------------------------------------------------
// Means of share-branch projections over the graph nodes (per modality).
// ---------------------------------------------------------------------------
__global__ void mean_kernel(const float* __restrict__ x,
                            float* __restrict__ hgi, float* __restrict__ hgt)
{
    int b = blockIdx.x, p = threadIdx.x;   // 384 threads
    const float* xb = x + (size_t)b * NN * P_;
    float s = 0.f;
    for (int i = 0; i < I_; i++) s += xb[(size_t)i * P_ + p];
    hgi[(size_t)b * P_ + p] = s / (float)I_;
    s = 0.f;
    for (int t = 0; t < T_; t++) s += xb[(size_t)(I_ + t) * P_ + p];
    hgt[(size_t)b * P_ + p] = s / (float)T_;
}

// ---------------------------------------------------------------------------
// Symmetric-KL per-batch partials (sum-reduced semantics, x0.5 at the end).
// Precise expf kept here: the losses are outputs built from cancellations.
// ---------------------------------------------------------------------------
__device__ __forceinline__ float blk_reduce(float v, float* sm, bool ismax)
{
    int tid = threadIdx.x;
    sm[tid] = v;
    __syncthreads();
    for (int s = 64; s; s >>= 1) {
        if (tid < s) sm[tid] = ismax ? fmaxf(sm[tid], sm[tid + s]) : sm[tid] + sm[tid + s];
        __syncthreads();
    }
    float r = sm[0];
    __syncthreads();
    return r;
}

__global__ __launch_bounds__(128)
void kl_kernel(const float* __restrict__ Pm, long long strideP,
               const float* __restrict__ Qm, long long strideQ,
               int D, float* __restrict__ partial)
{
    __shared__ float sm[128];
    const int b = blockIdx.x, tid = threadIdx.x;
    const float* p = Pm + (size_t)b * strideP;
    const float* q = Qm + (size_t)b * strideQ;

    float mp = -1e30f, mq = -1e30f;
    for (int d = tid; d < D; d += 128) { mp = fmaxf(mp, p[d]); mq = fmaxf(mq, q[d]); }
    mp = blk_reduce(mp, sm, true);
    mq = blk_reduce(mq, sm, true);

    float sp = 0.f, sq = 0.f;
    for (int d = tid; d < D; d += 128) { sp += expf(p[d] - mp); sq += expf(q[d] - mq); }
    sp = blk_reduce(sp, sm, false);
    sq = blk_reduce(sq, sm, false);
    float lsp = logf(sp), lsq = logf(sq);

    float acc = 0.f;
    for (int d = tid; d < D; d += 128) {
        float lp = p[d] - mp - lsp;
        float lq = q[d] - mq - lsq;
        acc += expf(lq) * (lq - lp) + expf(lp) * (lp - lq);
    }
    acc = blk_reduce(acc, sm, false);
    if (tid == 0) partial[b] = 0.5f * acc;
}

__global__ void sum32_kernel(const float* __restrict__ partial, float* __restrict__ out)
{
    if (threadIdx.x == 0) {
        float s = 0.f;
        for (int i = 0; i < B_; i++) s += partial[i];
        *out = s;
    }
}

// ---------------------------------------------------------------------------
// Host side
// ---------------------------------------------------------------------------
static void launch_gemm(int act, const float* A, const float* W, const float* bias,
                        float* C, int M, int K, int Nn, int rpb, int off, int nper)
{
    dim3 grid(Nn / BN, (M + BM - 1) / BM);
    if (act == 0)      gemm_kernel<0><<<grid, 256>>>(A, W, bias, C, M, K, Nn, rpb, off, nper);
    else if (act == 1) gemm_kernel<1><<<grid, 256>>>(A, W, bias, C, M, K, Nn, rpb, off, nper);
    else               gemm_kernel<2><<<grid, 256>>>(A, W, bias, C, M, K, Nn, rpb, off, nper);
}

extern "C" void kernel_launch(void* const* d_in, const int* in_sizes, int n_in,
                              void* d_out, int out_size)
{
    (void)in_sizes; (void)n_in; (void)out_size;

    const float* utt_t = (const float*)d_in[0];
    const float* utt_v = (const float*)d_in[1];
    const float* Wpt   = (const float*)d_in[2];
    const float* bpt   = (const float*)d_in[3];
    const float* Wpv   = (const float*)d_in[4];
    const float* bpv   = (const float*)d_in[5];
    const float* Ws    = (const float*)d_in[6];
    const float* bs    = (const float*)d_in[7];
    const float* Wproj = (const float*)d_in[8];
    const float* bproj = (const float*)d_in[9];
    const float* Wg    = (const float*)d_in[10];
    const float* al    = (const float*)d_in[11];
    const float* ar    = (const float*)d_in[12];
    const float* Wc    = (const float*)d_in[13];
    const float* bc    = (const float*)d_in[14];
    float* out = (float*)d_out;

    float* sc = nullptr;
    cudaGetSymbolAddress((void**)&sc, g_scratch);

    float* priv_t = sc + OFF_PRIV_T;
    float* priv_v = sc + OFF_PRIV_V;
    float* shar_t = sc + OFF_SHAR_T;
    float* shar_v = sc + OFF_SHAR_V;
    float* x      = sc + OFF_X;
    float* hbuf   = sc + OFF_H;
    float* gout   = sc + OFF_GOUT;
    float* el     = sc + OFF_EL;
    float* er     = sc + OFF_ER;
    float* hgi    = sc + OFF_HGI;
    float* hgt    = sc + OFF_HGT;
    float* klb    = sc + OFF_KL;

    // ---- sigmoid projections ----
    launch_gemm(1, utt_t, Wpt, bpt, priv_t, BT, H_, H_, 0, 0, 0);
    launch_gemm(1, utt_v, Wpv, bpv, priv_v, BI, H_, H_, 0, 0, 0);
    launch_gemm(1, utt_t, Ws,  bs,  shar_t, BT, H_, H_, 0, 0, 0);
    launch_gemm(1, utt_v, Ws,  bs,  shar_v, BI, H_, H_, 0, 0, 0);

    const dim3 gat_grid((NN + DT - 1) / DT, B_);
    const int  eler_grid = (BNN + 7) / 8;

    // ---- private branch ----
    launch_gemm(2, priv_v, Wproj, bproj, x, BI, H_, P_, I_, 0,  NN);
    launch_gemm(2, priv_t, Wproj, bproj, x, BT, H_, P_, T_, I_, NN);
    launch_gemm(0, x, Wg, nullptr, hbuf, BNN, P_, G_, 0, 0, 0);
    eler_kernel<<<eler_grid, 256>>>(hbuf, al, ar, el, er);
    gat_kernel<<<gat_grid, 256>>>(hbuf, el, er, gout);
    launch_gemm(0, gout, Wc, bc, out, BNN, G_, C_, 0, 0, 0);                 // private_emb

    // ---- share branch ----
    launch_gemm(2, shar_v, Wproj, bproj, x, BI, H_, P_, I_, 0,  NN);
    launch_gemm(2, shar_t, Wproj, bproj, x, BT, H_, P_, T_, I_, NN);
    mean_kernel<<<B_, P_>>>(x, hgi, hgt);
    launch_gemm(0, x, Wg, nullptr, hbuf, BNN, P_, G_, 0, 0, 0);
    eler_kernel<<<eler_grid, 256>>>(hbuf, al, ar, el, er);
    gat_kernel<<<gat_grid, 256>>>(hbuf, el, er, gout);
    launch_gemm(0, gout, Wc, bc, out + BNC, BNN, G_, C_, 0, 0, 0);           // share_emb

    // ---- losses ----
    kl_kernel<<<B_, 128>>>(hgi, P_, hgt, P_, P_, klb);
    sum32_kernel<<<1, 32>>>(klb, out + 2 * BNC);                             // share_loss
    kl_kernel<<<B_, 128>>>(out + BNC, (long long)NN * C_,
                           out,       (long long)NN * C_, C_, klb);
    sum32_kernel<<<1, 32>>>(klb, out + 2 * BNC + 1);                         // graph_loss
}

// round 14
// speedup vs baseline: 1.0731x; 1.0731x over previous
#include <cuda_runtime.h>
#include <math.h>

// ---------------------------------------------------------------------------
// Problem constants
// ---------------------------------------------------------------------------
constexpr int B_ = 32, T_ = 60, I_ = 577, H_ = 768, P_ = 384, G_ = 256, C_ = 128;
constexpr int NN  = I_ + T_;              // 637
constexpr int BT  = B_ * T_;              // 1920
constexpr int BI  = B_ * I_;              // 18464
constexpr int BNN = B_ * NN;              // 20384
constexpr size_t BNC = (size_t)BNN * C_;  // 2609152

// ---------------------------------------------------------------------------
// Packed fp32x2 helpers (sm_103a: fma.rn.f32x2 — 2 IEEE fp32 FMAs per issue)
// ---------------------------------------------------------------------------
__device__ __forceinline__ unsigned long long pack2(float v) {
    unsigned long long r;
    asm("mov.b64 %0, {%1, %1};" : "=l"(r) : "f"(v));
    return r;
}
__device__ __forceinline__ void fma2(unsigned long long& d,
                                     unsigned long long a, unsigned long long b) {
    asm("fma.rn.f32x2 %0, %1, %2, %0;" : "+l"(d) : "l"(a), "l"(b));
}
__device__ __forceinline__ float2 unpack2(unsigned long long v) {
    float2 f;
    asm("mov.b64 {%0, %1}, %2;" : "=f"(f.x), "=f"(f.y) : "l"(v));
    return f;
}

// ---------------------------------------------------------------------------
// Scratch layout (single static __device__ array; no allocations anywhere)
// ---------------------------------------------------------------------------
constexpr size_t SZ_PT = (size_t)BT * H_;
constexpr size_t SZ_PV = (size_t)BI * H_;
constexpr size_t SZ_X  = (size_t)BNN * P_;
constexpr size_t SZ_H  = (size_t)BNN * G_;

constexpr size_t OFF_PRIV_T = 0;
constexpr size_t OFF_PRIV_V = OFF_PRIV_T + SZ_PT;
constexpr size_t OFF_SHAR_T = OFF_PRIV_V + SZ_PV;
constexpr size_t OFF_SHAR_V = OFF_SHAR_T + SZ_PT;
constexpr size_t OFF_X      = OFF_SHAR_V + SZ_PV;
constexpr size_t OFF_H      = OFF_X + SZ_X;
constexpr size_t OFF_GOUT   = OFF_H + SZ_H;
constexpr size_t OFF_EL     = OFF_GOUT + SZ_H;
constexpr size_t OFF_ER     = OFF_EL + BNN;
constexpr size_t OFF_HGI    = OFF_ER + BNN;
constexpr size_t OFF_HGT    = OFF_HGI + (size_t)B_ * P_;
constexpr size_t OFF_KL     = OFF_HGT + (size_t)B_ * P_;
constexpr size_t SCRATCH_TOTAL = OFF_KL + 64;

__device__ float g_scratch[SCRATCH_TOTAL];

// ---------------------------------------------------------------------------
// GEMM: C = act(A[M,K] @ W[K,N] + bias), 128x128x8 tiling, 8x8 per thread,
// 256 threads, register-prefetch double buffering, packed f32x2 inner loop.
// Microtile is SPLIT 4+4 with the halves 64 apart (rows ty*4 / 64+ty*4,
// cols tx*4 / 64+tx*4): lanes 0-15 then read LDS.128 at 16B stride
// (contiguous 256B, conflict-free 2 phases) instead of 32B stride
// (4-way bank-group conflict, 4 phases) — fixes the measured L1=83.7%
// crossbar bottleneck from R9's profile.
// Optional output row remap for the concat([proj_v, proj_t]) layout:
//   orow = (row / rpb) * nper + off + row % rpb   (when rpb > 0)
// Requires: K % 8 == 0, N % 128 == 0 (true for all shapes here). M guarded.
// ---------------------------------------------------------------------------
constexpr int BM = 128, BN = 128, BKK = 8;

template<int ACT>  // 0 = none, 1 = sigmoid, 2 = relu
__global__ __launch_bounds__(256)
void gemm_kernel(const float* __restrict__ A, const float* __restrict__ W,
                 const float* __restrict__ bias, float* __restrict__ C,
                 int M, int K, int Nn, int rpb, int off, int nper)
{
    __shared__ __align__(16) float As[BKK][BM];   // transposed A tile: As[k][m]
    __shared__ __align__(16) float Bs[BKK][BN];   // Bs[k][n]

    const int tid = threadIdx.x;
    const int ty = tid >> 4, tx = tid & 15;        // 16x16 thread grid
    const int m0 = blockIdx.y * BM;
    const int n0 = blockIdx.x * BN;

    // A loader: 128 rows x 8 k -> 1 float4 per thread (along K)
    const int a_row = tid >> 1;            // 0..127
    const int a_kc  = (tid & 1) << 2;      // 0 or 4
    // B loader: 8 k-rows x 128 cols -> 1 float4 per thread (along N)
    const int b_kr  = tid >> 5;            // 0..7
    const int b_c   = (tid & 31) << 2;     // 0..124

    const bool a_ok = (m0 + a_row < M);
    const float* a_src = A + (size_t)(m0 + a_row) * K + a_kc;
    const float* b_src = W + (size_t)b_kr * Nn + n0 + b_c;

    // acc2[i][jp]: i<4 -> row ty*4+i, i>=4 -> row 64+ty*4+(i-4)
    //   jp 0,1 -> cols tx*4 + {0,1} / {2,3}
    //   jp 2,3 -> cols 64+tx*4 + {0,1} / {2,3}
    unsigned long long acc2[8][4];
    #pragma unroll
    for (int i = 0; i < 8; i++)
        #pragma unroll
        for (int j = 0; j < 4; j++) acc2[i][j] = 0ULL;

    // Prologue: fetch tile 0 into registers
    float4 a_pref = a_ok ? *(const float4*)(a_src)
                         : make_float4(0.f, 0.f, 0.f, 0.f);
    float4 b_pref = *(const float4*)(b_src);

    for (int k0 = 0; k0 < K; k0 += BKK) {
        // Deposit prefetched tile into smem
        As[a_kc + 0][a_row] = a_pref.x;
        As[a_kc + 1][a_row] = a_pref.y;
        As[a_kc + 2][a_row] = a_pref.z;
        As[a_kc + 3][a_row] = a_pref.w;
        *(float4*)&Bs[b_kr][b_c] = b_pref;
        __syncthreads();

        // Issue next tile's global loads before the compute loop
        const int kn = k0 + BKK;
        if (kn < K) {
            a_pref = a_ok ? *(const float4*)(a_src + kn)
                          : make_float4(0.f, 0.f, 0.f, 0.f);
            b_pref = *(const float4*)(b_src + (size_t)BKK * Nn);
            b_src += (size_t)BKK * Nn;
        }

        #pragma unroll
        for (int kk = 0; kk < BKK; kk++) {
            // 4+4 split operands: 16B-stride LDS.128 -> conflict-free
            float4 a0 = *(const float4*)&As[kk][ty << 2];         // rows ty*4..+3
            float4 a1 = *(const float4*)&As[kk][64 + (ty << 2)];  // rows 64+ty*4..+3
            ulonglong2 blo = *(const ulonglong2*)&Bs[kk][tx << 2];        // cols tx*4..+3
            ulonglong2 bhi = *(const ulonglong2*)&Bs[kk][64 + (tx << 2)]; // cols 64+tx*4..+3
            unsigned long long ap[8] = {
                pack2(a0.x), pack2(a0.y), pack2(a0.z), pack2(a0.w),
                pack2(a1.x), pack2(a1.y), pack2(a1.z), pack2(a1.w)
            };
            #pragma unroll
            for (int i = 0; i < 8; i++) {
                fma2(acc2[i][0], ap[i], blo.x);
                fma2(acc2[i][1], ap[i], blo.y);
                fma2(acc2[i][2], ap[i], bhi.x);
                fma2(acc2[i][3], ap[i], bhi.y);
            }
        }
        __syncthreads();
    }

    #pragma unroll
    for (int i = 0; i < 8; i++) {
        int rloc = (i < 4) ? ((ty << 2) + i) : (64 + (ty << 2) + (i - 4));
        int row = m0 + rloc;
        if (row >= M) continue;
        int orow = (rpb > 0) ? ((row / rpb) * nper + off + (row % rpb)) : row;
        float* crow = C + (size_t)orow * Nn;
        #pragma unroll
        for (int half = 0; half < 2; half++) {
            int cbase = n0 + half * 64 + (tx << 2);
            float2 p0 = unpack2(acc2[i][half * 2 + 0]);
            float2 p1 = unpack2(acc2[i][half * 2 + 1]);
            float cc[4] = {p0.x, p0.y, p1.x, p1.y};
            float4 v;
            float* vp = &v.x;
            #pragma unroll
            for (int j = 0; j < 4; j++) {
                float c = cc[j];
                if (bias) c += bias[cbase + j];
                if (ACT == 1) c = 1.f / (1.f + __expf(-c));
                if (ACT == 2) c = fmaxf(c, 0.f);
                vp[j] = c;
            }
            *(float4*)(crow + cbase) = v;
        }
    }
}

// ---------------------------------------------------------------------------
// el/er: per-row dot of h[row, :G] with al / ar. One warp per row.
// ---------------------------------------------------------------------------
__global__ void eler_kernel(const float* __restrict__ h,
                            const float* __restrict__ al,
                            const float* __restrict__ ar,
                            float* __restrict__ el, float* __restrict__ er)
{
    int row  = blockIdx.x * 8 + (threadIdx.x >> 5);
    int lane = threadIdx.x & 31;
    if (row >= BNN) return;
    const float* hr = h + (size_t)row * G_;
    float se = 0.f, sr = 0.f;
    #pragma unroll
    for (int j = 0; j < G_ / 32; j++) {
        float hv = hr[lane + 32 * j];
        se += hv * al[lane + 32 * j];
        sr += hv * ar[lane + 32 * j];
    }
    #pragma unroll
    for (int o = 16; o; o >>= 1) {
        se += __shfl_xor_sync(0xffffffffu, se, o);
        sr += __shfl_xor_sync(0xffffffffu, sr, o);
    }
    if (lane == 0) { el[row] = se; er[row] = sr; }
}

// ---------------------------------------------------------------------------
// Fused GAT: for each (b, dst): softmax over src != dst of
// leaky_relu(el[src] + er[dst]), then out[g] = elu(sum_src a * h[src,g]).
// One block handles DT=16 dst rows (each warp runs 2 softmaxes), then all
// 256 threads (g = tid) do the weighted sum with 16-way h reuse.
// s_w stored [src][16]; hot loop: 1 LDG + 4 LDS.128 + 1 pack + 8 FFMA2 / src.
// ---------------------------------------------------------------------------
constexpr int DT = 16;

__global__ __launch_bounds__(256)
void gat_kernel(const float* __restrict__ h, const float* __restrict__ el,
                const float* __restrict__ er, float* __restrict__ gout)
{
    __shared__ float s_el[NN];
    __shared__ __align__(16) float s_w[NN][DT];
    __shared__ float s_den[DT];

    const int b   = blockIdx.y;
    const int d0  = blockIdx.x * DT;
    const int tid = threadIdx.x;

    for (int i = tid; i < NN; i += 256) s_el[i] = el[(size_t)b * NN + i];
    __syncthreads();

    const int w = tid >> 5, lane = tid & 31;
    #pragma unroll
    for (int sub = 0; sub < 2; sub++) {
        const int dl  = w + sub * 8;     // 0..15
        const int dst = d0 + dl;
        if (dst < NN) {
            float erd = er[(size_t)b * NN + dst];
            float m = -1e30f;
            for (int src = lane; src < NN; src += 32) {
                if (src == dst) continue;
                float s  = s_el[src] + erd;
                float lr = s > 0.f ? s : 0.2f * s;
                m = fmaxf(m, lr);
            }
            #pragma unroll
            for (int o = 16; o; o >>= 1)
                m = fmaxf(m, __shfl_xor_sync(0xffffffffu, m, o));
            float den = 0.f;
            for (int src = lane; src < NN; src += 32) {
                float s  = s_el[src] + erd;
                float lr = s > 0.f ? s : 0.2f * s;
                float wv = (src == dst) ? 0.f : __expf(lr - m);
                s_w[src][dl] = wv;
                den += wv;
            }
            #pragma unroll
            for (int o = 16; o; o >>= 1)
                den += __shfl_xor_sync(0xffffffffu, den, o);
            if (lane == 0) s_den[dl] = den;
        } else {
            for (int src = lane; src < NN; src += 32) s_w[src][dl] = 0.f;
            if (lane == 0) s_den[dl] = 1.f;
        }
    }
    __syncthreads();

    // weighted sum: g = tid (G == 256 == blockDim); acc pairs over dst
    unsigned long long acc2[8];
    #pragma unroll
    for (int d = 0; d < 8; d++) acc2[d] = 0ULL;

    const float* hb = h + (size_t)b * NN * G_ + tid;
    for (int src = 0; src < NN; src++) {
        float hv = hb[(size_t)src * G_];
        unsigned long long hp = pack2(hv);
        ulonglong2 w01 = *(const ulonglong2*)&s_w[src][0];
        ulonglong2 w23 = *(const ulonglong2*)&s_w[src][4];
        ulonglong2 w45 = *(const ulonglong2*)&s_w[src][8];
        ulonglong2 w67 = *(const ulonglong2*)&s_w[src][12];
        fma2(acc2[0], hp, w01.x); fma2(acc2[1], hp, w01.y);
        fma2(acc2[2], hp, w23.x); fma2(acc2[3], hp, w23.y);
        fma2(acc2[4], hp, w45.x); fma2(acc2[5], hp, w45.y);
        fma2(acc2[6], hp, w67.x); fma2(acc2[7], hp, w67.y);
    }
    #pragma unroll
    for (int dp = 0; dp < 8; dp++) {
        float2 pr = unpack2(acc2[dp]);
        float av[2] = {pr.x, pr.y};
        #pragma unroll
        for (int half = 0; half < 2; half++) {
            int d = dp * 2 + half;
            int dst2 = d0 + d;
            if (dst2 < NN) {
                float o = av[half] / s_den[d];
                gout[((size_t)b * NN + dst2) * G_ + tid] = o > 0.f ? o : expm1f(o);
            }
        }
    }
}

// ---------------------------------------------------------------------------
// Means of share-branch projections over the graph nodes (per modality).
// ---------------------------------------------------------------------------
__global__ void mean_kernel(const float* __restrict__ x,
                            float* __restrict__ hgi, float* __restrict__ hgt)
{
    int b = blockIdx.x, p = threadIdx.x;   // 384 threads
    const float* xb = x + (size_t)b * NN * P_;
    float s = 0.f;
    for (int i = 0; i < I_; i++) s += xb[(size_t)i * P_ + p];
    hgi[(size_t)b * P_ + p] = s / (float)I_;
    s = 0.f;
    for (int t = 0; t < T_; t++) s += xb[(size_t)(I_ + t) * P_ + p];
    hgt[(size_t)b * P_ + p] = s / (float)T_;
}

// ---------------------------------------------------------------------------
// Symmetric-KL per-batch partials (sum-reduced semantics, x0.5 at the end).
// Precise expf kept here: the losses are outputs built from cancellations.
// ---------------------------------------------------------------------------
__device__ __forceinline__ float blk_reduce(float v, float* sm, bool ismax)
{
    int tid = threadIdx.x;
    sm[tid] = v;
    __syncthreads();
    for (int s = 64; s; s >>= 1) {
        if (tid < s) sm[tid] = ismax ? fmaxf(sm[tid], sm[tid + s]) : sm[tid] + sm[tid + s];
        __syncthreads();
    }
    float r = sm[0];
    __syncthreads();
    return r;
}

__global__ __launch_bounds__(128)
void kl_kernel(const float* __restrict__ Pm, long long strideP,
               const float* __restrict__ Qm, long long strideQ,
               int D, float* __restrict__ partial)
{
    __shared__ float sm[128];
    const int b = blockIdx.x, tid = threadIdx.x;
    const float* p = Pm + (size_t)b * strideP;
    const float* q = Qm + (size_t)b * strideQ;

    float mp = -1e30f, mq = -1e30f;
    for (int d = tid; d < D; d += 128) { mp = fmaxf(mp, p[d]); mq = fmaxf(mq, q[d]); }
    mp = blk_reduce(mp, sm, true);
    mq = blk_reduce(mq, sm, true);

    float sp = 0.f, sq = 0.f;
    for (int d = tid; d < D; d += 128) { sp += expf(p[d] - mp); sq += expf(q[d] - mq); }
    sp = blk_reduce(sp, sm, false);
    sq = blk_reduce(sq, sm, false);
    float lsp = logf(sp), lsq = logf(sq);

    float acc = 0.f;
    for (int d = tid; d < D; d += 128) {
        float lp = p[d] - mp - lsp;
        float lq = q[d] - mq - lsq;
        acc += expf(lq) * (lq - lp) + expf(lp) * (lp - lq);
    }
    acc = blk_reduce(acc, sm, false);
    if (tid == 0) partial[b] = 0.5f * acc;
}

__global__ void sum32_kernel(const float* __restrict__ partial, float* __restrict__ out)
{
    if (threadIdx.x == 0) {
        float s = 0.f;
        for (int i = 0; i < B_; i++) s += partial[i];
        *out = s;
    }
}

// ---------------------------------------------------------------------------
// Host side
// ---------------------------------------------------------------------------
static void launch_gemm(int act, const float* A, const float* W, const float* bias,
                        float* C, int M, int K, int Nn, int rpb, int off, int nper)
{
    dim3 grid(Nn / BN, (M + BM - 1) / BM);
    if (act == 0)      gemm_kernel<0><<<grid, 256>>>(A, W, bias, C, M, K, Nn, rpb, off, nper);
    else if (act == 1) gemm_kernel<1><<<grid, 256>>>(A, W, bias, C, M, K, Nn, rpb, off, nper);
    else               gemm_kernel<2><<<grid, 256>>>(A, W, bias, C, M, K, Nn, rpb, off, nper);
}

extern "C" void kernel_launch(void* const* d_in, const int* in_sizes, int n_in,
                              void* d_out, int out_size)
{
    (void)in_sizes; (void)n_in; (void)out_size;

    const float* utt_t = (const float*)d_in[0];
    const float* utt_v = (const float*)d_in[1];
    const float* Wpt   = (const float*)d_in[2];
    const float* bpt   = (const float*)d_in[3];
    const float* Wpv   = (const float*)d_in[4];
    const float* bpv   = (const float*)d_in[5];
    const float* Ws    = (const float*)d_in[6];
    const float* bs    = (const float*)d_in[7];
    const float* Wproj = (const float*)d_in[8];
    const float* bproj = (const float*)d_in[9];
    const float* Wg    = (const float*)d_in[10];
    const float* al    = (const float*)d_in[11];
    const float* ar    = (const float*)d_in[12];
    const float* Wc    = (const float*)d_in[13];
    const float* bc    = (const float*)d_in[14];
    float* out = (float*)d_out;

    float* sc = nullptr;
    cudaGetSymbolAddress((void**)&sc, g_scratch);

    float* priv_t = sc + OFF_PRIV_T;
    float* priv_v = sc + OFF_PRIV_V;
    float* shar_t = sc + OFF_SHAR_T;
    float* shar_v = sc + OFF_SHAR_V;
    float* x      = sc + OFF_X;
    float* hbuf   = sc + OFF_H;
    float* gout   = sc + OFF_GOUT;
    float* el     = sc + OFF_EL;
    float* er     = sc + OFF_ER;
    float* hgi    = sc + OFF_HGI;
    float* hgt    = sc + OFF_HGT;
    float* klb    = sc + OFF_KL;

    // ---- sigmoid projections ----
    launch_gemm(1, utt_t, Wpt, bpt, priv_t, BT, H_, H_, 0, 0, 0);
    launch_gemm(1, utt_v, Wpv, bpv, priv_v, BI, H_, H_, 0, 0, 0);
    launch_gemm(1, utt_t, Ws,  bs,  shar_t, BT, H_, H_, 0, 0, 0);
    launch_gemm(1, utt_v, Ws,  bs,  shar_v, BI, H_, H_, 0, 0, 0);

    const dim3 gat_grid((NN + DT - 1) / DT, B_);
    const int  eler_grid = (BNN + 7) / 8;

    // ---- private branch ----
    launch_gemm(2, priv_v, Wproj, bproj, x, BI, H_, P_, I_, 0,  NN);
    launch_gemm(2, priv_t, Wproj, bproj, x, BT, H_, P_, T_, I_, NN);
    launch_gemm(0, x, Wg, nullptr, hbuf, BNN, P_, G_, 0, 0, 0);
    eler_kernel<<<eler_grid, 256>>>(hbuf, al, ar, el, er);
    gat_kernel<<<gat_grid, 256>>>(hbuf, el, er, gout);
    launch_gemm(0, gout, Wc, bc, out, BNN, G_, C_, 0, 0, 0);                 // private_emb

    // ---- share branch ----
    launch_gemm(2, shar_v, Wproj, bproj, x, BI, H_, P_, I_, 0,  NN);
    launch_gemm(2, shar_t, Wproj, bproj, x, BT, H_, P_, T_, I_, NN);
    mean_kernel<<<B_, P_>>>(x, hgi, hgt);
    launch_gemm(0, x, Wg, nullptr, hbuf, BNN, P_, G_, 0, 0, 0);
    eler_kernel<<<eler_grid, 256>>>(hbuf, al, ar, el, er);
    gat_kernel<<<gat_grid, 256>>>(hbuf, el, er, gout);
    launch_gemm(0, gout, Wc, bc, out + BNC, BNN, G_, C_, 0, 0, 0);           // share_emb

    // ---- losses ----
    kl_kernel<<<B_, 128>>>(hgi, P_, hgt, P_, P_, klb);
    sum32_kernel<<<1, 32>>>(klb, out + 2 * BNC);                             // share_loss
    kl_kernel<<<B_, 128>>>(out + BNC, (long long)NN * C_,
                           out,       (long long)NN * C_, C_, klb);
    sum32_kernel<<<1, 32>>>(klb, out + 2 * BNC + 1);                         // graph_loss
}